// round 6
// baseline (speedup 1.0000x reference)
#include <cuda_runtime.h>

// Fused SSIM for GB300 (sm_103a). Single kernel launch.
// img1, img2 : (16, 3, 512, 512) fp32; channel 0, crop [4:508) -> 504x504,
// 11x11 zero-padded box filters, SSIM map, global mean -> 1 fp32 scalar.
//
// This version: packed f32x2 math (even/odd window-sum trick), 2 rows
// ingested per barrier, 4-deep smem row buffering, register h-ring.

typedef unsigned long long ull;

#define IMG_H 512
#define IMG_W 512
#define CROP 4
#define OH 504
#define OW 504
#define NB 16
#define KHALF 5

#define ROWS_PER_STRIP 56
#define NSTRIPS 9              // 9 * 56 = 504
#define THREADS 256
#define NCOLT 252              // threads 0..251 own 2 output columns each
#define NBLOCKS (NSTRIPS * NB) // 144 blocks -> 1/SM, single wave
#define SROW 516               // 514 used (+2 zero tail) padded

__device__ double g_acc;          // zero-init at load; self-resetting
__device__ unsigned int g_count;

// ---------------- packed f32x2 helpers ----------------
__device__ __forceinline__ ull pack2(float x, float y) {
    ull r; asm("mov.b64 %0, {%1, %2};" : "=l"(r) : "f"(x), "f"(y)); return r;
}
__device__ __forceinline__ void unpack2(ull v, float& x, float& y) {
    asm("mov.b64 {%0, %1}, %2;" : "=f"(x), "=f"(y) : "l"(v));
}
__device__ __forceinline__ ull add2(ull a, ull b) {
    ull r; asm("add.rn.f32x2 %0, %1, %2;" : "=l"(r) : "l"(a), "l"(b)); return r;
}
__device__ __forceinline__ ull mul2(ull a, ull b) {
    ull r; asm("mul.rn.f32x2 %0, %1, %2;" : "=l"(r) : "l"(a), "l"(b)); return r;
}
__device__ __forceinline__ ull fma2(ull a, ull b, ull c) {
    ull r; asm("fma.rn.f32x2 %0, %1, %2, %3;" : "=l"(r) : "l"(a), "l"(b), "l"(c)); return r;
}

// ---------------- per-row global prefetch ----------------
// smem j maps cropped col (j-5), global col (j-1); valid j in [5,509).
// Thread t stages j = t and j = t+256 (zero outside valid range).
__device__ __forceinline__ void load_row(const float* __restrict__ base1,
                                         const float* __restrict__ base2,
                                         int cr, int t,
                                         float& a0, float& a1,
                                         float& b0, float& b1)
{
    a0 = a1 = b0 = b1 = 0.0f;
    if (cr >= 0 && cr < OH) {
        const float* r1 = base1 + (size_t)(cr + CROP) * IMG_W;
        const float* r2 = base2 + (size_t)(cr + CROP) * IMG_W;
        if (t >= KHALF) { a0 = r1[t - 1];   b0 = r2[t - 1]; }
        if (t < 253)    { a1 = r1[t + 255]; b1 = r2[t + 255]; }
    }
}

// ---------------- horizontal window sums, both cols packed ----------------
// p1/p2 point at smem float index c (c even). Taps j = c .. c+11 as 6 u64.
// Output o[q] = packed (col0, col1) for q in {Sa, Sb, Saa, Sbb, Sab}.
__device__ __forceinline__ void hsums(const float* __restrict__ p1,
                                      const float* __restrict__ p2,
                                      ull o[5])
{
    const ull* q1 = reinterpret_cast<const ull*>(p1);
    const ull* q2 = reinterpret_cast<const ull*>(p2);
    ull va[6], vb[6];
    #pragma unroll
    for (int i = 0; i < 6; i++) { va[i] = q1[i]; vb[i] = q2[i]; }

    ull Pa = va[0], Pb = vb[0];
    ull Qa = mul2(va[0], va[0]);
    ull Qb = mul2(vb[0], vb[0]);
    ull R  = mul2(va[0], vb[0]);
    #pragma unroll
    for (int i = 1; i < 6; i++) {
        Pa = add2(Pa, va[i]);
        Pb = add2(Pb, vb[i]);
        Qa = fma2(va[i], va[i], Qa);
        Qb = fma2(vb[i], vb[i], Qb);
        R  = fma2(va[i], vb[i], R);
    }
    float a0, a1x, a10x, a11, b0, b1x, b10x, b11;
    unpack2(va[0], a0, a1x);  unpack2(va[5], a10x, a11);
    unpack2(vb[0], b0, b1x);  unpack2(vb[5], b10x, b11);

    float px, py, qx, qy, rx, ry;
    unpack2(Pa, px, py); float sa = px + py;           // sum taps 0..11 (a)
    unpack2(Pb, px, py); float sb = px + py;
    unpack2(Qa, qx, qy); float qa = qx + qy;
    unpack2(Qb, qx, qy); float qb = qx + qy;
    unpack2(R,  rx, ry); float rr = rx + ry;

    o[0] = pack2(sa - a11, sa - a0);
    o[1] = pack2(sb - b11, sb - b0);
    o[2] = pack2(fmaf(-a11, a11, qa), fmaf(-a0, a0, qa));
    o[3] = pack2(fmaf(-b11, b11, qb), fmaf(-b0, b0, qb));
    o[4] = pack2(fmaf(-a11, b11, rr), fmaf(-a0, b0, rr));
}

// ---------------- packed SSIM for one output row (2 cols) ----------------
__device__ __forceinline__ float ssim2(const ull vs[5], ull INV2, ull M1_2,
                                       ull C1_2, ull C2_2)
{
    ull m1  = mul2(vs[0], INV2);
    ull m2  = mul2(vs[1], INV2);
    ull m11 = mul2(m1, m1);
    ull m22 = mul2(m2, m2);
    ull m12 = mul2(m1, m2);
    ull nm1 = mul2(m1, M1_2);
    ull nm2 = mul2(m2, M1_2);
    ull s11 = fma2(nm1, m1, mul2(vs[2], INV2));
    ull s22 = fma2(nm2, m2, mul2(vs[3], INV2));
    ull s12 = fma2(nm1, m2, mul2(vs[4], INV2));
    ull num = mul2(add2(add2(m12, m12), C1_2), add2(add2(s12, s12), C2_2));
    ull den = mul2(add2(add2(m11, m22), C1_2), add2(add2(s11, s22), C2_2));
    float n0, n1, d0, d1;
    unpack2(num, n0, n1);
    unpack2(den, d0, d1);
    return __fdividef(n0, d0) + __fdividef(n1, d1);
}

__global__ __launch_bounds__(THREADS, 1)
void ssim_main(const float* __restrict__ img1,
               const float* __restrict__ img2,
               float* __restrict__ out)
{
    // [pair-parity][row-in-pair][col]
    __shared__ __align__(16) float sm1[2][2][SROW];
    __shared__ __align__(16) float sm2[2][2][SROW];
    __shared__ float warp_sums[THREADS / 32];

    const int t = threadIdx.x;
    const int strip = blockIdx.x;
    const int b = blockIdx.y;
    const int r0 = strip * ROWS_PER_STRIP;

    const float* base1 = img1 + (size_t)b * 3 * IMG_H * IMG_W;
    const float* base2 = img2 + (size_t)b * 3 * IMG_H * IMG_W;

    const bool active = (t < NCOLT);
    const int c = 2 * t;

    // zero tails j = 512..515, all 8 row-buffers (never re-stored)
    if (t < 4) {
        #pragma unroll
        for (int pp = 0; pp < 2; pp++)
            #pragma unroll
            for (int rr = 0; rr < 2; rr++) {
                sm1[pp][rr][512 + t] = 0.0f;
                sm2[pp][rr][512 + t] = 0.0f;
            }
    }

    const ull INV2 = pack2(1.0f / 121.0f, 1.0f / 121.0f);
    const ull M1_2 = pack2(-1.0f, -1.0f);
    const ull C1_2 = pack2(6.5025f, 6.5025f);     // (0.01*255)^2
    const ull C2_2 = pack2(58.5225f, 58.5225f);   // (0.03*255)^2

    ull h[5][11];   // h-ring: packed (col0,col1) horizontal sums, 11 rows
    ull vs[5];      // packed vertical running sums over the 11-row window
    #pragma unroll
    for (int q = 0; q < 5; q++) vs[q] = 0ULL;

    float acc0 = 0.0f, acc1 = 0.0f;

    // prefetch pair 0 (ingest rows n=0,1 -> cropped rows r0-5, r0-4)
    float pa00, pa01, pb00, pb01, pa10, pa11, pb10, pb11;
    load_row(base1, base2, r0 - KHALF + 0, t, pa00, pa01, pb00, pb01);
    load_row(base1, base2, r0 - KHALF + 1, t, pa10, pa11, pb10, pb11);

    // ---------- warmup: pairs m=0..4 ingest rows n=0..9 into slots 0..9 ----------
    #pragma unroll
    for (int m = 0; m < 5; m++) {
        const int par = m & 1;
        sm1[par][0][t] = pa00; sm1[par][0][t + 256] = pa01;
        sm2[par][0][t] = pb00; sm2[par][0][t + 256] = pb01;
        sm1[par][1][t] = pa10; sm1[par][1][t + 256] = pa11;
        sm2[par][1][t] = pb10; sm2[par][1][t + 256] = pb11;
        // prefetch pair m+1 (LDGs in flight across compute)
        load_row(base1, base2, r0 - KHALF + 2 * m + 2, t, pa00, pa01, pb00, pb01);
        load_row(base1, base2, r0 - KHALF + 2 * m + 3, t, pa10, pa11, pb10, pb11);
        __syncthreads();
        if (active) {
            ull o0[5], o1[5];
            hsums(&sm1[par][0][c], &sm2[par][0][c], o0);
            hsums(&sm1[par][1][c], &sm2[par][1][c], o1);
            #pragma unroll
            for (int q = 0; q < 5; q++) {
                h[q][2 * m]     = o0[q];
                h[q][2 * m + 1] = o1[q];
                vs[q] = add2(vs[q], add2(o0[q], o1[q]));
            }
        }
    }

    // ---------- main: pairs m=5..32, outputs k=2m-10, 2m-9 ----------
    int m = 5;
    #pragma unroll 1
    for (int outer = 0; outer < 3; outer++) {
        #pragma unroll
        for (int mm = 0; mm < 11; mm++) {
            if (m > 32) break;
            const int par = m & 1;
            sm1[par][0][t] = pa00; sm1[par][0][t + 256] = pa01;
            sm2[par][0][t] = pb00; sm2[par][0][t + 256] = pb01;
            sm1[par][1][t] = pa10; sm1[par][1][t + 256] = pa11;
            sm2[par][1][t] = pb10; sm2[par][1][t + 256] = pb11;
            load_row(base1, base2, r0 - KHALF + 2 * m + 2, t, pa00, pa01, pb00, pb01);
            load_row(base1, base2, r0 - KHALF + 2 * m + 3, t, pa10, pa11, pb10, pb11);
            __syncthreads();
            if (active) {
                ull o0[5], o1[5];
                hsums(&sm1[par][0][c], &sm2[par][0][c], o0);
                hsums(&sm1[par][1][c], &sm2[par][1][c], o1);
                // slot arithmetic: 2m ≡ 2mm+10 (mod 11) for all three outer bases
                const int sA = (2 * mm + 10) % 11;  // store h(row n=2m)
                const int sB = (2 * mm) % 11;       // leave row 2m-10; then store h(2m+1)
                const int sC = (2 * mm + 1) % 11;   // leave row 2m-9
                #pragma unroll
                for (int q = 0; q < 5; q++) vs[q] = add2(vs[q], o0[q]);
                acc0 += ssim2(vs, INV2, M1_2, C1_2, C2_2);
                #pragma unroll
                for (int q = 0; q < 5; q++) {
                    vs[q] = fma2(h[q][sB], M1_2, vs[q]);
                    h[q][sA] = o0[q];
                }
                #pragma unroll
                for (int q = 0; q < 5; q++) vs[q] = add2(vs[q], o1[q]);
                acc1 += ssim2(vs, INV2, M1_2, C1_2, C2_2);
                #pragma unroll
                for (int q = 0; q < 5; q++) {
                    vs[q] = fma2(h[q][sC], M1_2, vs[q]);
                    h[q][sB] = o1[q];
                }
            }
            m++;
        }
    }

    // ---------- reduction: warp shuffle -> smem -> one atomicAdd per block ----------
    float acc = acc0 + acc1;
    #pragma unroll
    for (int off = 16; off > 0; off >>= 1)
        acc += __shfl_down_sync(0xFFFFFFFFu, acc, off);
    if ((t & 31) == 0) warp_sums[t >> 5] = acc;
    __syncthreads();

    if (t == 0) {
        float s = 0.0f;
        #pragma unroll
        for (int w = 0; w < THREADS / 32; w++) s += warp_sums[w];
        atomicAdd(&g_acc, (double)s);
        __threadfence();
        unsigned int cnt = atomicAdd(&g_count, 1u);
        if (cnt == (unsigned int)(NBLOCKS - 1)) {
            double v = atomicAdd(&g_acc, 0.0);
            out[0] = (float)(v * (1.0 / ((double)NB * OH * OW)));
            // self-reset so every graph replay starts clean
            g_acc = 0.0;
            g_count = 0u;
        }
    }
}

extern "C" void kernel_launch(void* const* d_in, const int* in_sizes, int n_in,
                              void* d_out, int out_size)
{
    const float* img1 = (const float*)d_in[0];
    const float* img2 = (const float*)d_in[1];
    float* out = (float*)d_out;

    dim3 grid(NSTRIPS, NB);
    ssim_main<<<grid, THREADS>>>(img1, img2, out);
}

// round 11
// speedup vs baseline: 1.1750x; 1.1750x over previous
#include <cuda_runtime.h>

// Fused SSIM for GB300 (sm_103a). Single kernel launch.
// img1, img2 : (16, 3, 512, 512) fp32; channel 0, crop [4:508) -> 504x504,
// 11x11 zero-padded box filters, SSIM map, global mean -> 1 fp32 scalar.
//
// Vertical-first restructure: per-thread raw register ring (11 rows x 2 cols,
// packed f32x2) + 5 packed vertical running sums; horizontal 11-window done
// once per row via a smem exchange of vertical sums using the pair-sum trick.
// ~100 regs/thread -> 2 CTAs/SM (16 warps) for latency hiding.

typedef unsigned long long ull;

#define IMG_H 512
#define IMG_W 512
#define CROP 4
#define OH 504
#define OW 504
#define NB 16
#define KHALF 5

#define ROWS_PER_STRIP 28
#define NSTRIPS 18             // 18 * 28 = 504
#define THREADS 256
#define NCOLT 252              // threads 0..251 own 2 output columns each
#define NBLOCKS (NSTRIPS * NB) // 288 blocks; 2 CTAs/SM -> single wave
#define PADL 8                 // left zero-pad slots in exchange arrays
#define XN 268                 // 8 + 256 + 4 pad

__device__ double g_acc;          // zero-init at load; self-resetting
__device__ unsigned int g_count;

// ---------------- packed f32x2 helpers ----------------
__device__ __forceinline__ ull pack2(float x, float y) {
    ull r; asm("mov.b64 %0, {%1, %2};" : "=l"(r) : "f"(x), "f"(y)); return r;
}
__device__ __forceinline__ void unpack2(ull v, float& x, float& y) {
    asm("mov.b64 {%0, %1}, %2;" : "=f"(x), "=f"(y) : "l"(v));
}
__device__ __forceinline__ ull add2(ull a, ull b) {
    ull r; asm("add.rn.f32x2 %0, %1, %2;" : "=l"(r) : "l"(a), "l"(b)); return r;
}
__device__ __forceinline__ ull mul2(ull a, ull b) {
    ull r; asm("mul.rn.f32x2 %0, %1, %2;" : "=l"(r) : "l"(a), "l"(b)); return r;
}
__device__ __forceinline__ ull fma2(ull a, ull b, ull c) {
    ull r; asm("fma.rn.f32x2 %0, %1, %2, %3;" : "=l"(r) : "l"(a), "l"(b), "l"(c)); return r;
}

// Load this thread's 2 columns (cropped cols 2t, 2t+1) of cropped row cr.
__device__ __forceinline__ void load_pair(const float* __restrict__ base1,
                                          const float* __restrict__ base2,
                                          int cr, int t, ull& A, ull& B)
{
    A = 0ULL; B = 0ULL;
    if (cr >= 0 && cr < OH && t < NCOLT) {
        const float2* r1 = reinterpret_cast<const float2*>(
            base1 + (size_t)(cr + CROP) * IMG_W + CROP + 2 * t);
        const float2* r2 = reinterpret_cast<const float2*>(
            base2 + (size_t)(cr + CROP) * IMG_W + CROP + 2 * t);
        float2 v1 = *r1;
        float2 v2 = *r2;
        A = pack2(v1.x, v1.y);
        B = pack2(v2.x, v2.y);
    }
}

// Packed SSIM for one output row (2 cols). win[q] = packed window sums.
__device__ __forceinline__ float ssim2(const ull win[5], ull INV2, ull M1_2,
                                       ull C1_2, ull C2_2)
{
    ull m1  = mul2(win[0], INV2);
    ull m2  = mul2(win[1], INV2);
    ull m11 = mul2(m1, m1);
    ull m22 = mul2(m2, m2);
    ull m12 = mul2(m1, m2);
    ull nm1 = mul2(m1, M1_2);
    ull nm2 = mul2(m2, M1_2);
    ull s11 = fma2(nm1, m1, mul2(win[2], INV2));
    ull s22 = fma2(nm2, m2, mul2(win[3], INV2));
    ull s12 = fma2(nm1, m2, mul2(win[4], INV2));
    ull num = mul2(add2(add2(m12, m12), C1_2), add2(add2(s12, s12), C2_2));
    ull den = mul2(add2(add2(m11, m22), C1_2), add2(add2(s11, s22), C2_2));
    float n0, n1, d0, d1;
    unpack2(num, n0, n1);
    unpack2(den, d0, d1);
    return __fdividef(n0, d0) + __fdividef(n1, d1);
}

__global__ __launch_bounds__(THREADS, 2)
void ssim_main(const float* __restrict__ img1,
               const float* __restrict__ img2,
               float* __restrict__ out)
{
    // Exchange buffers (double-buffered by row parity):
    //   Vs[par][q][idx] = packed vertical sums (col 2t, col 2t+1)
    //   Ps[par][q][idx] = V(2t) + V(2t+1)
    __shared__ ull   Vs[2][5][XN];
    __shared__ float Ps[2][5][XN];
    __shared__ float warp_sums[THREADS / 32];

    const int t = threadIdx.x;
    const int strip = blockIdx.x;
    const int b = blockIdx.y;
    const int r0 = strip * ROWS_PER_STRIP;
    const int idx = t + PADL;

    const float* base1 = img1 + (size_t)b * 3 * IMG_H * IMG_W;
    const float* base2 = img2 + (size_t)b * 3 * IMG_H * IMG_W;

    const bool active = (t < NCOLT);

    // zero the pad regions once (never re-stored)
    if (t < PADL) {
        #pragma unroll
        for (int pp = 0; pp < 2; pp++)
            #pragma unroll
            for (int q = 0; q < 5; q++) {
                Vs[pp][q][t] = 0ULL;        Ps[pp][q][t] = 0.0f;
                Vs[pp][q][260 + t] = 0ULL;  Ps[pp][q][260 + t] = 0.0f;
            }
    }
    __syncthreads();

    const ull INV2 = pack2(1.0f / 121.0f, 1.0f / 121.0f);
    const ull M1_2 = pack2(-1.0f, -1.0f);
    const ull C1_2 = pack2(6.5025f, 6.5025f);     // (0.01*255)^2
    const ull C2_2 = pack2(58.5225f, 58.5225f);   // (0.03*255)^2

    ull ringA[11], ringB[11];   // raw pixel ring (packed 2 cols), 44 regs
    ull V[5];                   // packed vertical running sums
    #pragma unroll
    for (int q = 0; q < 5; q++) V[q] = 0ULL;

    float acc = 0.0f;

    // Pipeline prologue: prefetch ingested row n=0 (cropped r0-5).
    ull curA, curB, pfA, pfB;
    load_pair(base1, base2, r0 - KHALF, t, curA, curB);

    // ---------- warmup: ingest rows n=0..9 (cropped r0-5 .. r0+4) ----------
    #pragma unroll
    for (int w = 0; w < 10; w++) {
        load_pair(base1, base2, r0 - KHALF + w + 1, t, pfA, pfB);  // in flight
        V[0] = add2(V[0], curA);
        V[1] = add2(V[1], curB);
        V[2] = fma2(curA, curA, V[2]);
        V[3] = fma2(curB, curB, V[3]);
        V[4] = fma2(curA, curB, V[4]);
        ringA[w] = curA; ringB[w] = curB;
        curA = pfA; curB = pfB;
    }

    // ---------- main: k = 0..27, output cropped row r0+k ----------
    #pragma unroll 1
    for (int bs = 0; bs < ROWS_PER_STRIP; bs += 11) {
        #pragma unroll
        for (int kk = 0; kk < 11; kk++) {
            const int k = bs + kk;
            if (k >= ROWS_PER_STRIP) break;
            const int par = k & 1;
            const int sNew = (kk + 10) % 11;  // ingested n=k+10 (mod-11 slot)
            const int sOld = kk % 11;         // ingested n=k leaves the window

            // prefetch next ingested row (cropped r0+k+6)
            load_pair(base1, base2, r0 + k + KHALF + 1, t, pfA, pfB);

            // add new row -> V covers cropped rows k-5..k+5
            V[0] = add2(V[0], curA);
            V[1] = add2(V[1], curB);
            V[2] = fma2(curA, curA, V[2]);
            V[3] = fma2(curB, curB, V[3]);
            V[4] = fma2(curA, curB, V[4]);

            // publish V and pair-sums P
            #pragma unroll
            for (int q = 0; q < 5; q++) {
                float vx, vy;
                unpack2(V[q], vx, vy);
                Vs[par][q][idx] = V[q];
                Ps[par][q][idx] = vx + vy;
            }
            __syncthreads();

            // horizontal 11-window for both cols:
            // col 2t  : S5 + V(2t-5)  (odd half of Vs[idx-3])
            // col 2t+1: S5 + V(2t+6)  (even half of Vs[idx+3])
            ull win[5];
            #pragma unroll
            for (int q = 0; q < 5; q++) {
                const float* Pq = Ps[par][q];
                float S5 = Pq[idx - 2] + Pq[idx - 1] + Pq[idx] +
                           Pq[idx + 1] + Pq[idx + 2];
                float e0 = reinterpret_cast<const float*>(&Vs[par][q][idx - 3])[1];
                float e1 = reinterpret_cast<const float*>(&Vs[par][q][idx + 3])[0];
                win[q] = pack2(S5 + e0, S5 + e1);
            }
            if (active)
                acc += ssim2(win, INV2, M1_2, C1_2, C2_2);

            // retire row k (cropped k-5) from V; rotate ring
            {
                ull oA = ringA[sOld], oB = ringB[sOld];
                ull nA = mul2(oA, M1_2), nB = mul2(oB, M1_2);
                V[0] = add2(V[0], nA);
                V[1] = add2(V[1], nB);
                V[2] = fma2(oA, nA, V[2]);
                V[3] = fma2(oB, nB, V[3]);
                V[4] = fma2(oA, nB, V[4]);
            }
            ringA[sNew] = curA; ringB[sNew] = curB;
            curA = pfA; curB = pfB;
        }
    }

    // ---------- reduction: warp shuffle -> smem -> one atomicAdd per block ----------
    #pragma unroll
    for (int off = 16; off > 0; off >>= 1)
        acc += __shfl_down_sync(0xFFFFFFFFu, acc, off);
    if ((t & 31) == 0) warp_sums[t >> 5] = acc;
    __syncthreads();

    if (t == 0) {
        float s = 0.0f;
        #pragma unroll
        for (int w = 0; w < THREADS / 32; w++) s += warp_sums[w];
        atomicAdd(&g_acc, (double)s);
        __threadfence();
        unsigned int cnt = atomicAdd(&g_count, 1u);
        if (cnt == (unsigned int)(NBLOCKS - 1)) {
            double v = atomicAdd(&g_acc, 0.0);
            out[0] = (float)(v * (1.0 / ((double)NB * OH * OW)));
            // self-reset so every graph replay starts clean
            g_acc = 0.0;
            g_count = 0u;
        }
    }
}

extern "C" void kernel_launch(void* const* d_in, const int* in_sizes, int n_in,
                              void* d_out, int out_size)
{
    const float* img1 = (const float*)d_in[0];
    const float* img2 = (const float*)d_in[1];
    float* out = (float*)d_out;

    dim3 grid(NSTRIPS, NB);
    ssim_main<<<grid, THREADS>>>(img1, img2, out);
}